// round 1
// baseline (speedup 1.0000x reference)
#include <cuda_runtime.h>
#include <math.h>

typedef unsigned long long ull;

#define M_TOTAL 131072  // 2048 windows * 64 tokens

// Scratch (device globals: allocation-guard safe)
__device__ float g_qkv[(size_t)M_TOTAL * 768];   // (B*N, 3*C) qkv activations
__device__ float g_ao[(size_t)M_TOTAL * 256];    // attention output, (B*N, C)
__device__ float g_bias16[8 * 64 * 64];          // 16*sigmoid(rpb), (H, N, N)

// ---------- packed f32x2 helpers (FFMA2 path, 2x fp32 throughput) ----------
__device__ __forceinline__ ull f2pack(float lo, float hi) {
    ull d; asm("mov.b64 %0, {%1, %2};" : "=l"(d) : "f"(lo), "f"(hi)); return d;
}
__device__ __forceinline__ float2 f2unpack(ull v) {
    float2 r; asm("mov.b64 {%0, %1}, %2;" : "=f"(r.x), "=f"(r.y) : "l"(v)); return r;
}
__device__ __forceinline__ ull f2fma(ull a, ull b, ull c) {
    ull d; asm("fma.rn.f32x2 %0, %1, %2, %3;" : "=l"(d) : "l"(a), "l"(b), "l"(c)); return d;
}
__device__ __forceinline__ ull f2add(ull a, ull b) {
    ull d; asm("add.rn.f32x2 %0, %1, %2;" : "=l"(d) : "l"(a), "l"(b)); return d;
}

// ---------- prep: CPB MLP -> 16*sigmoid(relative position bias) ----------
__global__ void prep_kernel(const float* __restrict__ cpb_w1,
                            const float* __restrict__ cpb_b1,
                            const float* __restrict__ cpb_w2) {
    __shared__ float bt[225][8];
    const int t = threadIdx.x;
    if (t < 225) {
        int i = t / 15, j = t % 15;
        float t0 = (float)(i - 7) * (8.0f / 7.0f);
        float t1 = (float)(j - 7) * (8.0f / 7.0f);
        t0 = copysignf(log2f(fabsf(t0) + 1.0f), t0) * (1.0f / 3.0f);
        t1 = copysignf(log2f(fabsf(t1) + 1.0f), t1) * (1.0f / 3.0f);
        float acc[8];
#pragma unroll
        for (int hh = 0; hh < 8; hh++) acc[hh] = 0.0f;
        for (int u = 0; u < 512; u++) {
            float hu = cpb_w1[2 * u] * t0 + cpb_w1[2 * u + 1] * t1 + cpb_b1[u];
            hu = fmaxf(hu, 0.0f);
#pragma unroll
            for (int hh = 0; hh < 8; hh++) acc[hh] += cpb_w2[hh * 512 + u] * hu;
        }
#pragma unroll
        for (int hh = 0; hh < 8; hh++) bt[t][hh] = acc[hh];
    }
    __syncthreads();
    for (int idx = t; idx < 8 * 64 * 64; idx += 256) {
        int hh = idx >> 12;
        int n = (idx >> 6) & 63;
        int m = idx & 63;
        int rid = ((n >> 3) - (m >> 3) + 7) * 15 + ((n & 7) - (m & 7) + 7);
        float v = bt[rid][hh];
        g_bias16[idx] = 16.0f / (1.0f + __expf(-v));
    }
}

// ---------- generic 64x64x(K=256) fp32 GEMM, Y = A @ W^T + bias ----------
// MODE==1: A = Ap (x), Y = g_qkv, bias = [q_bias, 0, v_bias] (b0=q_bias, b1=v_bias)
// MODE==0: A = g_ao,   Y = Yp,    bias = b0
// smem stored k-major with xor swizzle: conflict-free transpose stores and
// conflict-free float4 reads. Inner loop: 8 FFMA2 + ~3 LDS-cycles per k per warp.
template <int MODE>
__global__ __launch_bounds__(256) void gemm64_kernel(
    const float* __restrict__ Ap, const float* __restrict__ W,
    const float* __restrict__ b0, const float* __restrict__ b1,
    float* __restrict__ Yp, int Ncols)
{
    const float* A = (MODE == 1) ? Ap : g_ao;
    float* Y = (MODE == 1) ? g_qkv : Yp;

    __shared__ __align__(16) float sA[32 * 64];
    __shared__ __align__(16) float sB[32 * 64];

    const int t = threadIdx.x;
    const int tr = t >> 4;       // 0..15 (row group)
    const int tc = t & 15;       // 0..15 (col group)
    const int bm = blockIdx.x * 64;
    const int bn = blockIdx.y * 64;

    ull acc[4][2];
#pragma unroll
    for (int i = 0; i < 4; i++) { acc[i][0] = 0ULL; acc[i][1] = 0ULL; }

    for (int k0 = 0; k0 < 256; k0 += 32) {
#pragma unroll
        for (int i = 0; i < 2; i++) {
            int idx = t + i * 256;         // 0..511
            int row = idx >> 3;            // 0..63
            int c4 = (idx & 7) << 2;       // 0,4,...,28
            float4 av = *(const float4*)(A + (size_t)(bm + row) * 256 + k0 + c4);
            float4 wv = *(const float4*)(W + (size_t)(bn + row) * 256 + k0 + c4);
            float va[4] = {av.x, av.y, av.z, av.w};
            float vw[4] = {wv.x, wv.y, wv.z, wv.w};
#pragma unroll
            for (int q = 0; q < 4; q++) {
                int k = c4 + q;
                int off = k * 64 + ((((row >> 2) ^ (k >> 2)) & 15) << 2) + (row & 3);
                sA[off] = va[q];
                sB[off] = vw[q];
            }
        }
        __syncthreads();
#pragma unroll
        for (int k = 0; k < 32; k++) {
            int sw = k >> 2;
            float4 av = *(const float4*)(sA + k * 64 + (((tr ^ sw) & 15) << 2));
            ulonglong2 bv = *(const ulonglong2*)(sB + k * 64 + (((tc ^ sw) & 15) << 2));
            ull a0 = f2pack(av.x, av.x);
            ull a1 = f2pack(av.y, av.y);
            ull a2 = f2pack(av.z, av.z);
            ull a3 = f2pack(av.w, av.w);
            acc[0][0] = f2fma(a0, bv.x, acc[0][0]);
            acc[0][1] = f2fma(a0, bv.y, acc[0][1]);
            acc[1][0] = f2fma(a1, bv.x, acc[1][0]);
            acc[1][1] = f2fma(a1, bv.y, acc[1][1]);
            acc[2][0] = f2fma(a2, bv.x, acc[2][0]);
            acc[2][1] = f2fma(a2, bv.y, acc[2][1]);
            acc[3][0] = f2fma(a3, bv.x, acc[3][0]);
            acc[3][1] = f2fma(a3, bv.y, acc[3][1]);
        }
        __syncthreads();
    }

    const int col0 = bn + (tc << 2);
    float bias[4];
#pragma unroll
    for (int q = 0; q < 4; q++) {
        int cidx = col0 + q;
        if (MODE == 1) {
            bias[q] = (cidx < 256) ? b0[cidx] : ((cidx < 512) ? 0.0f : b1[cidx - 512]);
        } else {
            bias[q] = b0[cidx];
        }
    }
#pragma unroll
    for (int i = 0; i < 4; i++) {
        size_t row = (size_t)(bm + (tr << 2) + i);
        float2 p0 = f2unpack(acc[i][0]);
        float2 p1 = f2unpack(acc[i][1]);
        float4 o = make_float4(p0.x + bias[0], p0.y + bias[1], p1.x + bias[2], p1.y + bias[3]);
        *(float4*)(Y + row * (size_t)Ncols + col0) = o;
    }
}

// ---------- attention: one block per (window b, head h) ----------
__global__ __launch_bounds__(256) void attn_kernel(const float* __restrict__ logit_scale) {
    const int b = blockIdx.x;
    const int h = blockIdx.y;
    __shared__ __align__(16) float sq[64 * 36];
    __shared__ __align__(16) float sk[64 * 36];
    __shared__ __align__(16) float sv[64 * 36];
    __shared__ float s_scale;
    const int t = threadIdx.x;

    const float* base = g_qkv + (size_t)b * (64 * 768) + h * 32;
#pragma unroll
    for (int i = 0; i < 2; i++) {
        int idx = t + i * 256;
        int n = idx >> 3;
        int d4 = (idx & 7) << 2;
        const float* rb = base + n * 768 + d4;
        float4 qv = *(const float4*)(rb);
        float4 kv = *(const float4*)(rb + 256);
        float4 vv = *(const float4*)(rb + 512);
        *(float4*)(sq + n * 36 + d4) = qv;
        *(float4*)(sk + n * 36 + d4) = kv;
        *(float4*)(sv + n * 36 + d4) = vv;
    }
    if (t == 0) s_scale = __expf(fminf(logit_scale[h], 4.6051702f));  // min(ls, log(100))
    __syncthreads();

    // normalize q (fold in logit scale) and k rows
    if (t < 128) {
        float* row = (t < 64) ? (sq + t * 36) : (sk + (t - 64) * 36);
        float s = 0.0f;
#pragma unroll
        for (int d = 0; d < 32; d++) s += row[d] * row[d];
        float inv = 1.0f / fmaxf(sqrtf(s), 1e-12f);
        if (t < 64) inv *= s_scale;
#pragma unroll
        for (int d = 0; d < 32; d++) row[d] *= inv;
    }
    __syncthreads();

    const int n = t >> 2;   // row 0..63 (4 threads per row)
    const int c = t & 3;

    ull qr[16];
    {
        const float* qrow = sq + n * 36;
#pragma unroll
        for (int i = 0; i < 8; i++) {
            ulonglong2 qv = *(const ulonglong2*)(qrow + i * 4);
            qr[2 * i] = qv.x;
            qr[2 * i + 1] = qv.y;
        }
    }

    const float* bias = g_bias16 + ((h * 64 + n) * 64);
    float scr[16];
#pragma unroll
    for (int j = 0; j < 16; j++) {
        int m = (j << 2) + c;
        const float* krow = sk + m * 36;
        ull acc0 = 0ULL, acc1 = 0ULL;
#pragma unroll
        for (int i = 0; i < 8; i++) {
            ulonglong2 kv = *(const ulonglong2*)(krow + i * 4);
            acc0 = f2fma(qr[2 * i], kv.x, acc0);
            acc1 = f2fma(qr[2 * i + 1], kv.y, acc1);
        }
        float2 a0 = f2unpack(acc0);
        float2 a1 = f2unpack(acc1);
        scr[j] = a0.x + a0.y + a1.x + a1.y + bias[m];
    }

    // softmax over 64 columns (16 regs x 4 threads)
    float mx = scr[0];
#pragma unroll
    for (int j = 1; j < 16; j++) mx = fmaxf(mx, scr[j]);
    mx = fmaxf(mx, __shfl_xor_sync(0xffffffffu, mx, 1));
    mx = fmaxf(mx, __shfl_xor_sync(0xffffffffu, mx, 2));
    float sum = 0.0f;
#pragma unroll
    for (int j = 0; j < 16; j++) { scr[j] = __expf(scr[j] - mx); sum += scr[j]; }
    sum += __shfl_xor_sync(0xffffffffu, sum, 1);
    sum += __shfl_xor_sync(0xffffffffu, sum, 2);
    float rs = 1.0f / sum;
#pragma unroll
    for (int j = 0; j < 16; j++) scr[j] *= rs;

    // out[n][:] = sum_m attn[n][m] * v[m][:]
    ull oacc[16];
#pragma unroll
    for (int i = 0; i < 16; i++) oacc[i] = 0ULL;
#pragma unroll
    for (int j = 0; j < 16; j++) {
        int m = (j << 2) + c;
        ull p = f2pack(scr[j], scr[j]);
        const float* vrow = sv + m * 36;
#pragma unroll
        for (int i = 0; i < 8; i++) {
            ulonglong2 vv = *(const ulonglong2*)(vrow + i * 4);
            oacc[2 * i] = f2fma(p, vv.x, oacc[2 * i]);
            oacc[2 * i + 1] = f2fma(p, vv.y, oacc[2 * i + 1]);
        }
    }
#pragma unroll
    for (int i = 0; i < 16; i++) {
        oacc[i] = f2add(oacc[i], __shfl_xor_sync(0xffffffffu, oacc[i], 1));
        oacc[i] = f2add(oacc[i], __shfl_xor_sync(0xffffffffu, oacc[i], 2));
    }

    // write: thread c owns d in [c*8, c*8+8)
    float* orow = g_ao + (size_t)(b * 64 + n) * 256 + h * 32 + c * 8;
    ulonglong2 w0, w1;
    w0.x = oacc[c * 4 + 0]; w0.y = oacc[c * 4 + 1];
    w1.x = oacc[c * 4 + 2]; w1.y = oacc[c * 4 + 3];
    *(ulonglong2*)(orow) = w0;
    *(ulonglong2*)(orow + 4) = w1;
}

extern "C" void kernel_launch(void* const* d_in, const int* in_sizes, int n_in,
                              void* d_out, int out_size) {
    const float* x           = (const float*)d_in[0];
    const float* qkv_w       = (const float*)d_in[1];
    const float* q_bias      = (const float*)d_in[2];
    const float* v_bias      = (const float*)d_in[3];
    const float* logit_scale = (const float*)d_in[4];
    const float* cpb_w1      = (const float*)d_in[5];
    const float* cpb_b1      = (const float*)d_in[6];
    const float* cpb_w2      = (const float*)d_in[7];
    const float* proj_w      = (const float*)d_in[8];
    const float* proj_b      = (const float*)d_in[9];
    float* out = (float*)d_out;

    prep_kernel<<<1, 256>>>(cpb_w1, cpb_b1, cpb_w2);
    gemm64_kernel<1><<<dim3(M_TOTAL / 64, 12), 256>>>(x, qkv_w, q_bias, v_bias, nullptr, 768);
    attn_kernel<<<dim3(2048, 8), 256>>>(logit_scale);
    gemm64_kernel<0><<<dim3(M_TOTAL / 64, 4), 256>>>(nullptr, proj_w, proj_b, nullptr, out, 256);
}